// round 8
// baseline (speedup 1.0000x reference)
#include <cuda_runtime.h>
#include <cstdint>
#include <cmath>

// ---------------------------------------------------------------------------
// ResidualConvLSTM2D  (B=4, T=16, H=W=64, Cin=32, F=64)
// Round 7: FFMA2 conv + double-buffered cp.async k-chunk pipeline.
// ---------------------------------------------------------------------------

#define B_   4
#define T_   16
#define WW   64
#define HW   4096
#define CIN_X 32
#define F_   64
#define COUT 256
#define FRAMES 64

typedef unsigned long long u64;

#define FMA_F32X2(d, a, b, c) \
    asm("fma.rn.f32x2 %0, %1, %2, %3;" : "=l"(d) : "l"(a), "l"(b), "l"(c))

__device__ __forceinline__ u64 bcast_f32x2(float v) {
    u64 r; unsigned u = __float_as_uint(v);
    asm("mov.b64 %0, {%1, %1};" : "=l"(r) : "r"(u));
    return r;
}
__device__ __forceinline__ void unpack_f32x2(u64 v, float& lo, float& hi) {
    unsigned a, b;
    asm("mov.b64 {%0, %1}, %2;" : "=r"(a), "=r"(b) : "l"(v));
    lo = __uint_as_float(a); hi = __uint_as_float(b);
}
__device__ __forceinline__ uint32_t smem_u32(const void* p) {
    uint32_t a;
    asm("{ .reg .u64 t; cvta.to.shared.u64 t, %1; cvt.u32.u64 %0, t; }" : "=r"(a) : "l"(p));
    return a;
}
// 16B async copy; zero-fills smem when valid==false (src_size=0)
__device__ __forceinline__ void cp16z(uint32_t dst, const void* src, bool valid) {
    int sz = valid ? 16 : 0;
    asm volatile("cp.async.cg.shared.global [%0], [%1], 16, %2;" :: "r"(dst), "l"(src), "r"(sz));
}
#define CP_COMMIT() asm volatile("cp.async.commit_group;" ::: "memory")
#define CP_WAIT(n)  asm volatile("cp.async.wait_group %0;" :: "n"(n) : "memory")

// Scratch (allocation-free rule: __device__ globals)
__device__ float g_xplanar[FRAMES * CIN_X * HW];
__device__ float g_zx[FRAMES * COUT * HW];         // [frame][oc][pix]
__device__ float g_zs[B_ * COUT * HW];             // [b][oc][pix]
__device__ float g_h [B_ * F_ * HW];               // [b][f][pix]
__device__ float g_c [B_ * F_ * HW];               // [b][f][pix]

// ---------------------------------------------------------------------------
__global__ void zero_hc_kernel() {
    int g = blockIdx.x * 256 + threadIdx.x;
    if (g < B_ * F_ * HW) { g_h[g] = 0.f; g_c[g] = 0.f; }
}

// ---------------------------------------------------------------------------
__global__ void pack_x_kernel(const float* __restrict__ x) {
    __shared__ float s[256 * 33];
    int frame = blockIdx.y;
    int pix0  = blockIdx.x * 256;
    const float* src = x + (size_t)frame * (HW * CIN_X) + (size_t)pix0 * CIN_X;
    for (int i = threadIdx.x; i < 256 * CIN_X; i += 256) {
        int p = i >> 5, ci = i & 31;
        s[p * 33 + ci] = src[i];
    }
    __syncthreads();
    for (int i = threadIdx.x; i < 256 * CIN_X; i += 256) {
        int p = i & 255, ci = i >> 8;
        g_xplanar[((size_t)frame * CIN_X + ci) * HW + pix0 + p] = s[p * 33 + ci];
    }
}

// ---------------------------------------------------------------------------
__global__ void residual_kernel(const float* __restrict__ x,
                                const float* __restrict__ Wp,
                                const float* __restrict__ bp,
                                float* __restrict__ out) {
    __shared__ float sW[CIN_X * F_];
    __shared__ float sb[F_];
    for (int i = threadIdx.x; i < CIN_X * F_; i += 256) sW[i] = Wp[i];
    if (threadIdx.x < F_) sb[threadIdx.x] = bp[threadIdx.x];
    __syncthreads();

    int g = blockIdx.x * 256 + threadIdx.x;
    float xv[CIN_X];
    const float4* xp = (const float4*)(x + (size_t)g * CIN_X);
    #pragma unroll
    for (int i = 0; i < CIN_X / 4; i++) {
        float4 v = xp[i];
        xv[4*i] = v.x; xv[4*i+1] = v.y; xv[4*i+2] = v.z; xv[4*i+3] = v.w;
    }
    float* op = out + (size_t)g * F_;
    #pragma unroll 4
    for (int f = 0; f < F_; f++) {
        float a = sb[f];
        #pragma unroll
        for (int ci = 0; ci < CIN_X; ci++)
            a = fmaf(xv[ci], sW[ci * F_ + f], a);
        op[f] = a;
    }
}

// ---------------------------------------------------------------------------
// 3x3 SAME conv, planar, FFMA2, double-buffered cp.async pipeline.
// Block 256 thr = 32x8; tile 32x16 pixels; 32 oc/block.
// s_in buffer: [8 ci][18 rows][40 cols], col 0 = gx0-4 (16B-aligned halo).
// ---------------------------------------------------------------------------
#define IN_E (8 * 18 * 40)     // 5760 floats per buffer
#define W_E  (9 * 8 * 32)      // 2304 floats per buffer
#define IN_V4 (IN_E / 4)       // 1440
#define W_V4  (W_E / 4)        // 576
#define SMEM_CONV ((2 * IN_E + 2 * W_E) * 4)   // 64512 B

template<int CIN, int MODE>
__global__ __launch_bounds__(256, 2)
void conv3x3_kernel(const float* __restrict__ wsrc, const float* __restrict__ bias) {
    extern __shared__ float sm[];
    float* s_in[2] = { sm, sm + IN_E };
    float* s_w [2] = { sm + 2 * IN_E, sm + 2 * IN_E + W_E };

    const float* in  = (MODE == 0) ? g_xplanar : g_h;
    float*       out = (MODE == 0) ? g_zx      : g_zs;

    int tileX = blockIdx.x & 1;
    int tileY = blockIdx.x >> 1;
    int frame = blockIdx.y;
    int oc0   = blockIdx.z * 32;
    int tid   = threadIdx.x;
    int tx = tid & 31, ty = tid >> 5;
    int gx0 = tileX * 32, gy0 = tileY * 16;

    const size_t in_base = ((size_t)frame * CIN) << 12;

    // async-load one k-chunk (8 ci of input patch + 9x8x32 weights)
    auto issue = [&](int c0, int buf) {
        uint32_t din = smem_u32(s_in[buf]);
        uint32_t dw  = smem_u32(s_w[buf]);
        #pragma unroll 1
        for (int i = tid; i < IN_V4 + W_V4; i += 256) {
            if (i < IN_V4) {
                int seg = i % 10;
                int r   = i / 10;          // (ci*18 + yy)
                int yy  = r % 18, ci = r / 18;
                int gy  = gy0 + yy - 1;
                int gx  = gx0 - 4 + seg * 4;
                bool v  = ((unsigned)gy < 64u) & ((unsigned)gx <= 60u);
                const float* src = in + in_base + (((size_t)(c0 + ci)) << 12)
                                 + (v ? (gy * WW + gx) : 0);
                cp16z(din + (r * 40 + seg * 4) * 4, src, v);
            } else {
                int j = i - IN_V4;         // < 576
                int ocseg = j & 7, tc = j >> 3;       // tc = tap*8+ci
                int tap = tc >> 3, ci = tc & 7;
                const float* src = wsrc + (size_t)(tap * CIN + c0 + ci) * COUT
                                 + oc0 + ocseg * 4;
                cp16z(dw + j * 16, src, true);
            }
        }
        CP_COMMIT();
    };

    u64 acc0[16], acc1[16];
    #pragma unroll
    for (int i = 0; i < 16; i++) { acc0[i] = 0ull; acc1[i] = 0ull; }

    const int NCH = CIN / 8;
    issue(0, 0);

    #pragma unroll 1
    for (int cc = 0; cc < NCH; cc++) {
        int buf = cc & 1;
        if (cc + 1 < NCH) { issue((cc + 1) * 8, buf ^ 1); CP_WAIT(1); }
        else              { CP_WAIT(0); }
        __syncthreads();

        const float* bin = s_in[buf];
        const float* bw  = s_w[buf];

        #pragma unroll 1
        for (int dy = 0; dy < 3; dy++) {
            #pragma unroll
            for (int ci = 0; ci < 8; ci++) {
                const float* r0 = &bin[(ci * 18 + ty     + dy) * 40 + tx + 3];
                const float* r1 = &bin[(ci * 18 + ty + 8 + dy) * 40 + tx + 3];
                #pragma unroll
                for (int dx = 0; dx < 3; dx++) {
                    u64 i0 = bcast_f32x2(r0[dx]);
                    u64 i1 = bcast_f32x2(r1[dx]);
                    const ulonglong2* wp = (const ulonglong2*)&bw[((dy * 3 + dx) * 8 + ci) * 32];
                    #pragma unroll
                    for (int j = 0; j < 8; j++) {
                        ulonglong2 w2 = wp[j];
                        FMA_F32X2(acc0[2*j  ], i0, w2.x, acc0[2*j  ]);
                        FMA_F32X2(acc0[2*j+1], i0, w2.y, acc0[2*j+1]);
                        FMA_F32X2(acc1[2*j  ], i1, w2.x, acc1[2*j  ]);
                        FMA_F32X2(acc1[2*j+1], i1, w2.y, acc1[2*j+1]);
                    }
                }
            }
        }
        __syncthreads();   // buffer safe to overwrite next-next iteration
    }

    int p0 = (gy0 + ty) * WW + gx0 + tx;
    int p1 = p0 + 8 * WW;
    size_t obase = ((size_t)frame * COUT + oc0) << 12;
    #pragma unroll
    for (int j = 0; j < 16; j++) {
        float a0lo, a0hi, a1lo, a1hi;
        unpack_f32x2(acc0[j], a0lo, a0hi);
        unpack_f32x2(acc1[j], a1lo, a1hi);
        int oce = 2 * j, oco = 2 * j + 1;
        float bve = (MODE == 0) ? bias[oc0 + oce] : 0.f;
        float bvo = (MODE == 0) ? bias[oc0 + oco] : 0.f;
        out[obase + ((size_t)oce << 12) + p0] = a0lo + bve;
        out[obase + ((size_t)oco << 12) + p0] = a0hi + bvo;
        out[obase + ((size_t)oce << 12) + p1] = a1lo + bve;
        out[obase + ((size_t)oco << 12) + p1] = a1hi + bvo;
    }
}

// ---------------------------------------------------------------------------
// Gates + state + residual add (R2 mapping: 16 f per thread).
// ---------------------------------------------------------------------------
__global__ void gate_kernel(float* __restrict__ out, int t) {
    int g   = blockIdx.x * 256 + threadIdx.x;   // < 65536
    int q   = g & 3;
    int pix = (g >> 2) & 4095;
    int b   = g >> 14;
    int f0  = q * 16;
    int frame = b * T_ + t;

    size_t zxb = ((size_t)frame * COUT) << 12;
    size_t zsb = ((size_t)b * COUT) << 12;
    size_t cb  = (((size_t)b * F_)  << 12);
    float* op  = out + (((size_t)frame << 12) + pix) * F_;

    #pragma unroll
    for (int j = 0; j < 16; j++) {
        int f = f0 + j;
        float zi = g_zx[zxb + ((size_t)(f         ) << 12) + pix] + g_zs[zsb + ((size_t)(f         ) << 12) + pix];
        float zf = g_zx[zxb + ((size_t)(f +    F_ ) << 12) + pix] + g_zs[zsb + ((size_t)(f +    F_ ) << 12) + pix];
        float zc = g_zx[zxb + ((size_t)(f + 2 * F_) << 12) + pix] + g_zs[zsb + ((size_t)(f + 2 * F_) << 12) + pix];
        float zo = g_zx[zxb + ((size_t)(f + 3 * F_) << 12) + pix] + g_zs[zsb + ((size_t)(f + 3 * F_) << 12) + pix];

        float ig = __saturatef(fmaf(0.2f, zi, 0.5f));
        float fg = __saturatef(fmaf(0.2f, zf, 0.5f));
        float og = __saturatef(fmaf(0.2f, zo, 0.5f));

        float cold = g_c[cb + ((size_t)f << 12) + pix];
        float cnew = fmaf(fg, cold, ig * tanhf(zc));
        float h    = og * tanhf(cnew);

        g_c[cb + ((size_t)f << 12) + pix] = cnew;
        g_h[cb + ((size_t)f << 12) + pix] = h;
        op[f] = op[f] + h;
    }
}

// ---------------------------------------------------------------------------
extern "C" void kernel_launch(void* const* d_in, const int* in_sizes, int n_in,
                              void* d_out, int out_size) {
    const float* x  = (const float*)d_in[0];
    const float* Wx = (const float*)d_in[1];
    const float* Wh = (const float*)d_in[2];
    const float* b  = (const float*)d_in[3];
    const float* Wp = (const float*)d_in[4];
    const float* bp = (const float*)d_in[5];
    float* out = (float*)d_out;

    cudaFuncSetAttribute(conv3x3_kernel<CIN_X, 0>,
                         cudaFuncAttributeMaxDynamicSharedMemorySize, SMEM_CONV);
    cudaFuncSetAttribute(conv3x3_kernel<F_, 1>,
                         cudaFuncAttributeMaxDynamicSharedMemorySize, SMEM_CONV);

    zero_hc_kernel<<<(B_ * F_ * HW + 255) / 256, 256>>>();
    pack_x_kernel<<<dim3(16, FRAMES), 256>>>(x);
    residual_kernel<<<(FRAMES * HW) / 256, 256>>>(x, Wp, bp, out);
    conv3x3_kernel<CIN_X, 0><<<dim3(8, FRAMES, 8), 256, SMEM_CONV>>>(Wx, b);

    for (int t = 0; t < T_; t++) {
        conv3x3_kernel<F_, 1><<<dim3(8, B_, 8), 256, SMEM_CONV>>>(Wh, nullptr);
        gate_kernel<<<256, 256>>>(out, t);
    }
}

// round 9
// speedup vs baseline: 1.3763x; 1.3763x over previous
#include <cuda_runtime.h>
#include <cstdint>
#include <cmath>

// ---------------------------------------------------------------------------
// ResidualConvLSTM2D  (B=4, T=16, H=W=64, Cin=32, F=64)
// Round 8: R2 champion + vectorized (LDG.128) conv loader, L1-cached path.
// ---------------------------------------------------------------------------

#define B_   4
#define T_   16
#define WW   64
#define HW   4096
#define CIN_X 32
#define F_   64
#define COUT 256
#define FRAMES 64

typedef unsigned long long u64;

#define FMA_F32X2(d, a, b, c) \
    asm("fma.rn.f32x2 %0, %1, %2, %3;" : "=l"(d) : "l"(a), "l"(b), "l"(c))

__device__ __forceinline__ u64 bcast_f32x2(float v) {
    u64 r; unsigned u = __float_as_uint(v);
    asm("mov.b64 %0, {%1, %1};" : "=l"(r) : "r"(u));
    return r;
}
__device__ __forceinline__ void unpack_f32x2(u64 v, float& lo, float& hi) {
    unsigned a, b;
    asm("mov.b64 {%0, %1}, %2;" : "=r"(a), "=r"(b) : "l"(v));
    lo = __uint_as_float(a); hi = __uint_as_float(b);
}

// Scratch (allocation-free rule: __device__ globals)
__device__ float g_xplanar[FRAMES * CIN_X * HW];
__device__ float g_zx[FRAMES * COUT * HW];         // [frame][oc][pix]
__device__ float g_zs[B_ * COUT * HW];             // [b][oc][pix]
__device__ float g_h [B_ * F_ * HW];               // [b][f][pix]
__device__ float g_c [B_ * F_ * HW];               // [b][f][pix]

// ---------------------------------------------------------------------------
__global__ void zero_hc_kernel() {
    int g = blockIdx.x * 256 + threadIdx.x;
    if (g < B_ * F_ * HW) { g_h[g] = 0.f; g_c[g] = 0.f; }
}

// ---------------------------------------------------------------------------
__global__ void pack_x_kernel(const float* __restrict__ x) {
    __shared__ float s[256 * 33];
    int frame = blockIdx.y;
    int pix0  = blockIdx.x * 256;
    const float* src = x + (size_t)frame * (HW * CIN_X) + (size_t)pix0 * CIN_X;
    for (int i = threadIdx.x; i < 256 * CIN_X; i += 256) {
        int p = i >> 5, ci = i & 31;
        s[p * 33 + ci] = src[i];
    }
    __syncthreads();
    for (int i = threadIdx.x; i < 256 * CIN_X; i += 256) {
        int p = i & 255, ci = i >> 8;
        g_xplanar[((size_t)frame * CIN_X + ci) * HW + pix0 + p] = s[p * 33 + ci];
    }
}

// ---------------------------------------------------------------------------
__global__ void residual_kernel(const float* __restrict__ x,
                                const float* __restrict__ Wp,
                                const float* __restrict__ bp,
                                float* __restrict__ out) {
    __shared__ float sW[CIN_X * F_];
    __shared__ float sb[F_];
    for (int i = threadIdx.x; i < CIN_X * F_; i += 256) sW[i] = Wp[i];
    if (threadIdx.x < F_) sb[threadIdx.x] = bp[threadIdx.x];
    __syncthreads();

    int g = blockIdx.x * 256 + threadIdx.x;
    float xv[CIN_X];
    const float4* xp = (const float4*)(x + (size_t)g * CIN_X);
    #pragma unroll
    for (int i = 0; i < CIN_X / 4; i++) {
        float4 v = xp[i];
        xv[4*i] = v.x; xv[4*i+1] = v.y; xv[4*i+2] = v.z; xv[4*i+3] = v.w;
    }
    float* op = out + (size_t)g * F_;
    #pragma unroll 4
    for (int f = 0; f < F_; f++) {
        float a = sb[f];
        #pragma unroll
        for (int ci = 0; ci < CIN_X; ci++)
            a = fmaf(xv[ci], sW[ci * F_ + f], a);
        op[f] = a;
    }
}

// ---------------------------------------------------------------------------
// 3x3 SAME conv, planar, FFMA2.  Vectorized float4 loader:
// s_in [8 ci][18 rows][40 cols], col 0 = gx0-4 (16B-aligned; halo segments
// are all-or-nothing valid because 4 | 64).  Block 256 thr = 32x8;
// tile 32x16 pixels; 32 oc/block.
// ---------------------------------------------------------------------------
#define IN_E (8 * 18 * 40)     // 5760 floats
#define W_E  (9 * 8 * 32)      // 2304 floats
#define IN_V4 (IN_E / 4)       // 1440
#define W_V4  (W_E / 4)        // 576

template<int CIN, int MODE>
__global__ __launch_bounds__(256, 2)
void conv3x3_kernel(const float* __restrict__ wsrc, const float* __restrict__ bias) {
    __shared__ float s_in[IN_E];
    __shared__ float s_w [W_E];

    const float* in  = (MODE == 0) ? g_xplanar : g_h;
    float*       out = (MODE == 0) ? g_zx      : g_zs;

    int tileX = blockIdx.x & 1;
    int tileY = blockIdx.x >> 1;
    int frame = blockIdx.y;
    int oc0   = blockIdx.z * 32;
    int tid   = threadIdx.x;
    int tx = tid & 31, ty = tid >> 5;
    int gx0 = tileX * 32, gy0 = tileY * 16;

    const size_t in_base = ((size_t)frame * CIN) << 12;
    float4* s_in4 = (float4*)s_in;
    float4* s_w4  = (float4*)s_w;

    u64 acc0[16], acc1[16];
    #pragma unroll
    for (int i = 0; i < 16; i++) { acc0[i] = 0ull; acc1[i] = 0ull; }

    for (int c0 = 0; c0 < CIN; c0 += 8) {
        // ---- input patch: 1440 float4 (6 iters, last predicated) ----
        #pragma unroll
        for (int it = 0; it < 6; it++) {
            int i = it * 256 + tid;
            if (it < 5 || i < IN_V4) {
                int seg = i % 10;
                int r   = i / 10;               // ci*18 + yy
                int yy  = r % 18, ci = r / 18;
                int gy  = gy0 + yy - 1;
                int gx  = gx0 - 4 + seg * 4;
                float4 v = make_float4(0.f, 0.f, 0.f, 0.f);
                if (((unsigned)gy < 64u) & ((unsigned)gx < 64u))
                    v = *(const float4*)(in + in_base + (((size_t)(c0 + ci)) << 12) + gy * WW + gx);
                s_in4[r * 10 + seg] = v;
            }
        }
        // ---- weights: 576 float4 (3 iters, last predicated) ----
        #pragma unroll
        for (int it = 0; it < 3; it++) {
            int j = it * 256 + tid;
            if (it < 2 || j < W_V4) {
                int ocseg = j & 7;
                int tc    = j >> 3;             // tap*8 + ci
                int tap = tc >> 3, ci = tc & 7;
                s_w4[j] = *(const float4*)(wsrc + (size_t)(tap * CIN + c0 + ci) * COUT
                                           + oc0 + ocseg * 4);
            }
        }
        __syncthreads();

        #pragma unroll 1
        for (int tap = 0; tap < 9; tap++) {
            int dy = tap / 3, dx = tap - dy * 3;
            #pragma unroll
            for (int ci = 0; ci < 8; ci++) {
                u64 i0 = bcast_f32x2(s_in[(ci * 18 + ty     + dy) * 40 + tx + 3 + dx]);
                u64 i1 = bcast_f32x2(s_in[(ci * 18 + ty + 8 + dy) * 40 + tx + 3 + dx]);
                const ulonglong2* wp = (const ulonglong2*)&s_w[(tap * 8 + ci) * 32];
                #pragma unroll
                for (int j = 0; j < 8; j++) {
                    ulonglong2 w2 = wp[j];
                    FMA_F32X2(acc0[2*j  ], i0, w2.x, acc0[2*j  ]);
                    FMA_F32X2(acc0[2*j+1], i0, w2.y, acc0[2*j+1]);
                    FMA_F32X2(acc1[2*j  ], i1, w2.x, acc1[2*j  ]);
                    FMA_F32X2(acc1[2*j+1], i1, w2.y, acc1[2*j+1]);
                }
            }
        }
        __syncthreads();
    }

    int p0 = (gy0 + ty) * WW + gx0 + tx;
    int p1 = p0 + 8 * WW;
    size_t obase = ((size_t)frame * COUT + oc0) << 12;
    #pragma unroll
    for (int j = 0; j < 16; j++) {
        float a0lo, a0hi, a1lo, a1hi;
        unpack_f32x2(acc0[j], a0lo, a0hi);
        unpack_f32x2(acc1[j], a1lo, a1hi);
        int oce = 2 * j, oco = 2 * j + 1;
        float bve = (MODE == 0) ? bias[oc0 + oce] : 0.f;
        float bvo = (MODE == 0) ? bias[oc0 + oco] : 0.f;
        out[obase + ((size_t)oce << 12) + p0] = a0lo + bve;
        out[obase + ((size_t)oco << 12) + p0] = a0hi + bvo;
        out[obase + ((size_t)oce << 12) + p1] = a1lo + bve;
        out[obase + ((size_t)oco << 12) + p1] = a1hi + bvo;
    }
}

// ---------------------------------------------------------------------------
// Gates + state + residual add (R2 mapping: 16 f per thread).
// ---------------------------------------------------------------------------
__global__ void gate_kernel(float* __restrict__ out, int t) {
    int g   = blockIdx.x * 256 + threadIdx.x;   // < 65536
    int q   = g & 3;
    int pix = (g >> 2) & 4095;
    int b   = g >> 14;
    int f0  = q * 16;
    int frame = b * T_ + t;

    size_t zxb = ((size_t)frame * COUT) << 12;
    size_t zsb = ((size_t)b * COUT) << 12;
    size_t cb  = ((size_t)b * F_)   << 12;
    float* op  = out + (((size_t)frame << 12) + pix) * F_;

    #pragma unroll
    for (int j = 0; j < 16; j++) {
        int f = f0 + j;
        float zi = g_zx[zxb + ((size_t)(f         ) << 12) + pix] + g_zs[zsb + ((size_t)(f         ) << 12) + pix];
        float zf = g_zx[zxb + ((size_t)(f +    F_ ) << 12) + pix] + g_zs[zsb + ((size_t)(f +    F_ ) << 12) + pix];
        float zc = g_zx[zxb + ((size_t)(f + 2 * F_) << 12) + pix] + g_zs[zsb + ((size_t)(f + 2 * F_) << 12) + pix];
        float zo = g_zx[zxb + ((size_t)(f + 3 * F_) << 12) + pix] + g_zs[zsb + ((size_t)(f + 3 * F_) << 12) + pix];

        float ig = __saturatef(fmaf(0.2f, zi, 0.5f));
        float fg = __saturatef(fmaf(0.2f, zf, 0.5f));
        float og = __saturatef(fmaf(0.2f, zo, 0.5f));

        float cold = g_c[cb + ((size_t)f << 12) + pix];
        float cnew = fmaf(fg, cold, ig * tanhf(zc));
        float h    = og * tanhf(cnew);

        g_c[cb + ((size_t)f << 12) + pix] = cnew;
        g_h[cb + ((size_t)f << 12) + pix] = h;
        op[f] = op[f] + h;
    }
}

// ---------------------------------------------------------------------------
extern "C" void kernel_launch(void* const* d_in, const int* in_sizes, int n_in,
                              void* d_out, int out_size) {
    const float* x  = (const float*)d_in[0];
    const float* Wx = (const float*)d_in[1];
    const float* Wh = (const float*)d_in[2];
    const float* b  = (const float*)d_in[3];
    const float* Wp = (const float*)d_in[4];
    const float* bp = (const float*)d_in[5];
    float* out = (float*)d_out;

    zero_hc_kernel<<<(B_ * F_ * HW + 255) / 256, 256>>>();
    pack_x_kernel<<<dim3(16, FRAMES), 256>>>(x);
    residual_kernel<<<(FRAMES * HW) / 256, 256>>>(x, Wp, bp, out);
    conv3x3_kernel<CIN_X, 0><<<dim3(8, FRAMES, 8), 256>>>(Wx, b);

    for (int t = 0; t < T_; t++) {
        conv3x3_kernel<F_, 1><<<dim3(8, B_, 8), 256>>>(Wh, nullptr);
        gate_kernel<<<256, 256>>>(out, t);
    }
}

// round 10
// speedup vs baseline: 1.4371x; 1.0442x over previous
#include <cuda_runtime.h>
#include <cstdint>
#include <cmath>

// ---------------------------------------------------------------------------
// ResidualConvLSTM2D  (B=4, T=16, H=W=64, Cin=32, F=64)
// Round 9: FFMA2 conv, 64x16 tile (4 pixels/thread) -> half the load/barrier
// overhead per FLOP.
// ---------------------------------------------------------------------------

#define B_   4
#define T_   16
#define WW   64
#define HW   4096
#define CIN_X 32
#define F_   64
#define COUT 256
#define FRAMES 64

typedef unsigned long long u64;

#define FMA_F32X2(d, a, b, c) \
    asm("fma.rn.f32x2 %0, %1, %2, %3;" : "=l"(d) : "l"(a), "l"(b), "l"(c))

__device__ __forceinline__ u64 bcast_f32x2(float v) {
    u64 r; unsigned u = __float_as_uint(v);
    asm("mov.b64 %0, {%1, %1};" : "=l"(r) : "r"(u));
    return r;
}
__device__ __forceinline__ void unpack_f32x2(u64 v, float& lo, float& hi) {
    unsigned a, b;
    asm("mov.b64 {%0, %1}, %2;" : "=r"(a), "=r"(b) : "l"(v));
    lo = __uint_as_float(a); hi = __uint_as_float(b);
}

// Scratch (allocation-free rule: __device__ globals)
__device__ float g_xplanar[FRAMES * CIN_X * HW];
__device__ float g_zx[FRAMES * COUT * HW];         // [frame][oc][pix]
__device__ float g_zs[B_ * COUT * HW];             // [b][oc][pix]
__device__ float g_h [B_ * F_ * HW];               // [b][f][pix]
__device__ float g_c [B_ * F_ * HW];               // [b][f][pix]

// ---------------------------------------------------------------------------
__global__ void zero_hc_kernel() {
    int g = blockIdx.x * 256 + threadIdx.x;
    if (g < B_ * F_ * HW) { g_h[g] = 0.f; g_c[g] = 0.f; }
}

// ---------------------------------------------------------------------------
__global__ void pack_x_kernel(const float* __restrict__ x) {
    __shared__ float s[256 * 33];
    int frame = blockIdx.y;
    int pix0  = blockIdx.x * 256;
    const float* src = x + (size_t)frame * (HW * CIN_X) + (size_t)pix0 * CIN_X;
    for (int i = threadIdx.x; i < 256 * CIN_X; i += 256) {
        int p = i >> 5, ci = i & 31;
        s[p * 33 + ci] = src[i];
    }
    __syncthreads();
    for (int i = threadIdx.x; i < 256 * CIN_X; i += 256) {
        int p = i & 255, ci = i >> 8;
        g_xplanar[((size_t)frame * CIN_X + ci) * HW + pix0 + p] = s[p * 33 + ci];
    }
}

// ---------------------------------------------------------------------------
__global__ void residual_kernel(const float* __restrict__ x,
                                const float* __restrict__ Wp,
                                const float* __restrict__ bp,
                                float* __restrict__ out) {
    __shared__ float sW[CIN_X * F_];
    __shared__ float sb[F_];
    for (int i = threadIdx.x; i < CIN_X * F_; i += 256) sW[i] = Wp[i];
    if (threadIdx.x < F_) sb[threadIdx.x] = bp[threadIdx.x];
    __syncthreads();

    int g = blockIdx.x * 256 + threadIdx.x;
    float xv[CIN_X];
    const float4* xp = (const float4*)(x + (size_t)g * CIN_X);
    #pragma unroll
    for (int i = 0; i < CIN_X / 4; i++) {
        float4 v = xp[i];
        xv[4*i] = v.x; xv[4*i+1] = v.y; xv[4*i+2] = v.z; xv[4*i+3] = v.w;
    }
    float* op = out + (size_t)g * F_;
    #pragma unroll 4
    for (int f = 0; f < F_; f++) {
        float a = sb[f];
        #pragma unroll
        for (int ci = 0; ci < CIN_X; ci++)
            a = fmaf(xv[ci], sW[ci * F_ + f], a);
        op[f] = a;
    }
}

// ---------------------------------------------------------------------------
// 3x3 SAME conv, planar, FFMA2.  Tile 64(w) x 16(h), block 256 = 64x4,
// 4 pixels/thread (rows ty, ty+4, ty+8, ty+12), 32 oc/block.
// s_in: [8 ci][18 rows][72 cols], col 0 = x=-4 (16B-aligned halo; row spans
// x=-4..67, segments outside [0,60] start are zero-filled).
// ---------------------------------------------------------------------------
#define IN_E (8 * 18 * 72)     // 10368 floats
#define W_E  (9 * 8 * 32)      // 2304 floats
#define IN_V4 (IN_E / 4)       // 2592
#define W_V4  (W_E / 4)        // 576
#define SMEM_CONV ((IN_E + W_E) * 4)   // 50688 B

template<int CIN, int MODE>
__global__ __launch_bounds__(256, 1)
void conv3x3_kernel(const float* __restrict__ wsrc, const float* __restrict__ bias) {
    extern __shared__ float sm[];
    float* s_in = sm;
    float* s_w  = sm + IN_E;

    const float* in  = (MODE == 0) ? g_xplanar : g_h;
    float*       out = (MODE == 0) ? g_zx      : g_zs;

    int tileY = blockIdx.x;            // 0..3, 16 rows each
    int frame = blockIdx.y;
    int oc0   = blockIdx.z * 32;
    int tid   = threadIdx.x;
    int tx = tid & 63, ty = tid >> 6;  // 64 x 4
    int gy0 = tileY * 16;

    const size_t in_base = ((size_t)frame * CIN) << 12;
    float4* s_in4 = (float4*)s_in;
    float4* s_w4  = (float4*)s_w;

    u64 acc[4][16];
    #pragma unroll
    for (int r = 0; r < 4; r++)
        #pragma unroll
        for (int i = 0; i < 16; i++) acc[r][i] = 0ull;

    for (int c0 = 0; c0 < CIN; c0 += 8) {
        // ---- input patch: 2592 float4 (11 iters, last predicated) ----
        #pragma unroll
        for (int it = 0; it < 11; it++) {
            int i = it * 256 + tid;
            if (it < 10 || i < IN_V4) {
                int seg = i % 18;               // x = -4 + seg*4
                int r   = i / 18;               // ci*18 + yy
                int yy  = r % 18, ci = r / 18;
                int gy  = gy0 + yy - 1;
                int gx  = -4 + seg * 4;
                float4 v = make_float4(0.f, 0.f, 0.f, 0.f);
                if (((unsigned)gy < 64u) & ((unsigned)gx <= 60u))
                    v = *(const float4*)(in + in_base + (((size_t)(c0 + ci)) << 12) + gy * WW + gx);
                s_in4[r * 18 + seg] = v;
            }
        }
        // ---- weights: 576 float4 (3 iters, last predicated) ----
        #pragma unroll
        for (int it = 0; it < 3; it++) {
            int j = it * 256 + tid;
            if (it < 2 || j < W_V4) {
                int ocseg = j & 7;
                int tc    = j >> 3;             // tap*8 + ci
                int tap = tc >> 3, ci = tc & 7;
                s_w4[j] = *(const float4*)(wsrc + (size_t)(tap * CIN + c0 + ci) * COUT
                                           + oc0 + ocseg * 4);
            }
        }
        __syncthreads();

        #pragma unroll 1
        for (int tap = 0; tap < 9; tap++) {
            int dy = tap / 3, dx = tap - dy * 3;
            #pragma unroll
            for (int ci = 0; ci < 8; ci++) {
                u64 iv[4];
                #pragma unroll
                for (int r = 0; r < 4; r++)
                    iv[r] = bcast_f32x2(s_in[(ci * 18 + ty + 4 * r + dy) * 72 + tx + 3 + dx]);
                const ulonglong2* wp = (const ulonglong2*)&s_w[(tap * 8 + ci) * 32];
                #pragma unroll
                for (int j = 0; j < 8; j++) {
                    ulonglong2 w2 = wp[j];
                    #pragma unroll
                    for (int r = 0; r < 4; r++) {
                        FMA_F32X2(acc[r][2*j  ], iv[r], w2.x, acc[r][2*j  ]);
                        FMA_F32X2(acc[r][2*j+1], iv[r], w2.y, acc[r][2*j+1]);
                    }
                }
            }
        }
        __syncthreads();
    }

    size_t obase = ((size_t)frame * COUT + oc0) << 12;
    #pragma unroll
    for (int r = 0; r < 4; r++) {
        int p = (gy0 + ty + 4 * r) * WW + tx;
        #pragma unroll
        for (int j = 0; j < 16; j++) {
            float alo, ahi;
            unpack_f32x2(acc[r][j], alo, ahi);
            int oce = 2 * j, oco = 2 * j + 1;
            float bve = (MODE == 0) ? bias[oc0 + oce] : 0.f;
            float bvo = (MODE == 0) ? bias[oc0 + oco] : 0.f;
            out[obase + ((size_t)oce << 12) + p] = alo + bve;
            out[obase + ((size_t)oco << 12) + p] = ahi + bvo;
        }
    }
}

// ---------------------------------------------------------------------------
// Gates + state + residual add (R2 mapping: 16 f per thread).
// ---------------------------------------------------------------------------
__global__ void gate_kernel(float* __restrict__ out, int t) {
    int g   = blockIdx.x * 256 + threadIdx.x;   // < 65536
    int q   = g & 3;
    int pix = (g >> 2) & 4095;
    int b   = g >> 14;
    int f0  = q * 16;
    int frame = b * T_ + t;

    size_t zxb = ((size_t)frame * COUT) << 12;
    size_t zsb = ((size_t)b * COUT) << 12;
    size_t cb  = ((size_t)b * F_)   << 12;
    float* op  = out + (((size_t)frame << 12) + pix) * F_;

    #pragma unroll
    for (int j = 0; j < 16; j++) {
        int f = f0 + j;
        float zi = g_zx[zxb + ((size_t)(f         ) << 12) + pix] + g_zs[zsb + ((size_t)(f         ) << 12) + pix];
        float zf = g_zx[zxb + ((size_t)(f +    F_ ) << 12) + pix] + g_zs[zsb + ((size_t)(f +    F_ ) << 12) + pix];
        float zc = g_zx[zxb + ((size_t)(f + 2 * F_) << 12) + pix] + g_zs[zsb + ((size_t)(f + 2 * F_) << 12) + pix];
        float zo = g_zx[zxb + ((size_t)(f + 3 * F_) << 12) + pix] + g_zs[zsb + ((size_t)(f + 3 * F_) << 12) + pix];

        float ig = __saturatef(fmaf(0.2f, zi, 0.5f));
        float fg = __saturatef(fmaf(0.2f, zf, 0.5f));
        float og = __saturatef(fmaf(0.2f, zo, 0.5f));

        float cold = g_c[cb + ((size_t)f << 12) + pix];
        float cnew = fmaf(fg, cold, ig * tanhf(zc));
        float h    = og * tanhf(cnew);

        g_c[cb + ((size_t)f << 12) + pix] = cnew;
        g_h[cb + ((size_t)f << 12) + pix] = h;
        op[f] = op[f] + h;
    }
}

// ---------------------------------------------------------------------------
extern "C" void kernel_launch(void* const* d_in, const int* in_sizes, int n_in,
                              void* d_out, int out_size) {
    const float* x  = (const float*)d_in[0];
    const float* Wx = (const float*)d_in[1];
    const float* Wh = (const float*)d_in[2];
    const float* b  = (const float*)d_in[3];
    const float* Wp = (const float*)d_in[4];
    const float* bp = (const float*)d_in[5];
    float* out = (float*)d_out;

    cudaFuncSetAttribute(conv3x3_kernel<CIN_X, 0>,
                         cudaFuncAttributeMaxDynamicSharedMemorySize, SMEM_CONV);
    cudaFuncSetAttribute(conv3x3_kernel<F_, 1>,
                         cudaFuncAttributeMaxDynamicSharedMemorySize, SMEM_CONV);

    zero_hc_kernel<<<(B_ * F_ * HW + 255) / 256, 256>>>();
    pack_x_kernel<<<dim3(16, FRAMES), 256>>>(x);
    residual_kernel<<<(FRAMES * HW) / 256, 256>>>(x, Wp, bp, out);
    conv3x3_kernel<CIN_X, 0><<<dim3(4, FRAMES, 8), 256, SMEM_CONV>>>(Wx, b);

    for (int t = 0; t < T_; t++) {
        conv3x3_kernel<F_, 1><<<dim3(4, B_, 8), 256, SMEM_CONV>>>(Wh, nullptr);
        gate_kernel<<<256, 256>>>(out, t);
    }
}